// round 15
// baseline (speedup 1.0000x reference)
#include <cuda_runtime.h>
#include <cstdint>

// Correlation1dCost: feat [B,C,H,W] f32 -> out [B,D,H,W] f32
// out[b,d,y,x] = leakyrelu_0.1( sum_c f1[b,c,y,x] * f2[b,c,y,x+d-47] ), zero OOB
// Band-GEMM on tensor cores (m16n8k8 tf32); cp.async 4-stage depth-3 pipeline,
// chunk loop FULLY UNROLLED with compile-time stage indices.
// Hybrid grid: rows 0..911 = full-row CTAs; rows 912..1023 = half-row tail CTAs.
#define B_ 8
#define C_ 128
#define H_ 128
#define W_ 256
#define D_ 48
#define HW_ (H_ * W_)

#define CK 8               // channels per chunk = one k8 MMA step
#define NCH 16             // chunks
#define NSTG 4             // stages (power of two -> stage = k & 3)
#define S1S 264            // s1 row stride (words), %32==8 -> conflict-free frags
#define S2S 328            // s2 row stride (words), %32==8
#define S2OFF 48           // A-path: phys col = x' + 48
#define NT 256             // 8 warps
#define STG_S 260          // epilogue staging row stride

#define NA_CTAS 912
#define NB_ROWS (B_ * H_ - NA_CTAS)       // 112
#define GRID (NA_CTAS + 2 * NB_ROWS)      // 1136

#define STAGE_W (CK * (S1S + S2S))        // 4736 words
#define SMEM_BYTES (NSTG * STAGE_W * 4)   // 75776 B -> 2 CTAs/SM

extern __shared__ float smf[];

#define CP16(dst, src) asm volatile( \
    "cp.async.cg.shared.global [%0], [%1], 16;\n" :: "r"(dst), "l"(src))
#define CP_COMMIT() asm volatile("cp.async.commit_group;\n" ::: "memory")
#define CP_WAIT(n)  asm volatile("cp.async.wait_group %0;\n" :: "n"(n) : "memory")

__device__ __forceinline__ uint32_t cvt_tf32(uint32_t f) {
    uint32_t u;
    asm("cvt.rna.tf32.f32 %0, %1;" : "=r"(u) : "r"(f));
    return u;
}

__device__ __forceinline__ void mma_tf32(float d[4], const uint32_t a[4],
                                         uint32_t b0, uint32_t b1) {
    asm volatile(
        "mma.sync.aligned.m16n8k8.row.col.f32.tf32.tf32.f32 "
        "{%0,%1,%2,%3}, {%4,%5,%6,%7}, {%8,%9}, {%0,%1,%2,%3};"
        : "+f"(d[0]), "+f"(d[1]), "+f"(d[2]), "+f"(d[3])
        : "r"(a[0]), "r"(a[1]), "r"(a[2]), "r"(a[3]), "r"(b0), "r"(b1));
}

__device__ __forceinline__ float lrelu(float v) { return fmaxf(v, 0.1f * v); }

// compile-time wait: chunks <= K landed (issued = min(K+3, NCH))
template <int K> __device__ __forceinline__ void wait_ct() {
    constexpr int outstanding = (K + 3 < NCH ? K + 3 : NCH) - (K + 1);
    CP_WAIT(outstanding);
}

__global__ __launch_bounds__(NT, 2)
void corr1d_tc(const float* __restrict__ f1,
               const float* __restrict__ f2,
               float* __restrict__ out) {
    const int tid  = threadIdx.x;
    const int bid  = blockIdx.x;
    const int lane = tid & 31;
    const int w    = tid >> 5;
    const int gid  = lane >> 2;                // 0..7
    const int tig  = lane & 3;                 // 0..3
    const uint32_t smem_base = (uint32_t)__cvta_generic_to_shared(smf);

    // zero s2 left pads (phys cols [0,48)) for all stages ONCE
    for (int i = tid; i < NSTG * CK * S2OFF; i += NT) {
        int st = i / (CK * S2OFF);
        int r  = i % (CK * S2OFF);
        smf[st * STAGE_W + CK * S1S + (r / S2OFF) * S2S + (r % S2OFF)] = 0.0f;
    }

    if (bid < NA_CTAS) {
        // ================= A path: full row, warp = m32 =====================
        const int b  = bid >> 7;
        const int y  = bid & (H_ - 1);
        const int xw = 32 * w;

        const float* f1p = f1 + (b * C_ * H_ + y) * W_;
        const float* f2p = f2 + (b * C_ * H_ + y) * W_;

        const int qr = tid >> 6;               // 0..3 -> rows qr, qr+4
        const int qc = (tid & 63) * 4;         // 0..252

        // per-thread fill bases (stage offset + chunk offset folded as consts)
        const uint32_t s1d0 = smem_base + (qr * S1S + qc) * 4;
        const uint32_t s2d0 = smem_base + (CK * S1S + qr * S2S + S2OFF + qc) * 4;
        const float* g1 = f1p + qr * HW_ + qc;
        const float* g2 = f2p + qr * HW_ + qc;

        float frag[2][8][4];
#pragma unroll
        for (int i = 0; i < 2; ++i)
#pragma unroll
            for (int u = 0; u < 8; ++u)
#pragma unroll
                for (int c4 = 0; c4 < 4; ++c4) frag[i][u][c4] = 0.0f;

        // issue chunk K into stage K&3 (all offsets compile-time)
#define ISSUE_A(K) do { \
            constexpr int _st = (K) & 3; \
            const uint32_t _s1 = s1d0 + (_st * STAGE_W) * 4; \
            const uint32_t _s2 = s2d0 + (_st * STAGE_W) * 4; \
            CP16(_s1,                 g1 + (K) * CK * HW_); \
            CP16(_s1 + 4 * S1S * 4,   g1 + ((K) * CK + 4) * HW_); \
            CP16(_s2,                 g2 + (K) * CK * HW_); \
            CP16(_s2 + 4 * S2S * 4,   g2 + ((K) * CK + 4) * HW_); \
            CP_COMMIT(); \
        } while (0)

        ISSUE_A(0); ISSUE_A(1); ISSUE_A(2);

        const int a_off = tig * S1S + xw + gid;
        const int b_off = tig * S2S + xw + gid;

#define STEP_A(K) do { \
            wait_ct<K>(); \
            __syncthreads(); \
            if ((K) + 3 < NCH) ISSUE_A((K) + 3 < NCH ? (K) + 3 : 0); \
            constexpr int _st = (K) & 3; \
            const uint32_t* s1r = (const uint32_t*)(smf + _st * STAGE_W) + a_off; \
            const uint32_t* s2r = (const uint32_t*)(smf + _st * STAGE_W + CK * S1S) + b_off; \
            uint32_t A[2][4]; \
            _Pragma("unroll") \
            for (int i = 0; i < 2; ++i) { \
                A[i][0] = cvt_tf32(s1r[16 * i]); \
                A[i][1] = cvt_tf32(s1r[16 * i + 8]); \
                A[i][2] = cvt_tf32(s1r[4 * S1S + 16 * i]); \
                A[i][3] = cvt_tf32(s1r[4 * S1S + 16 * i + 8]); \
            } \
            uint32_t Bf[10][2]; \
            _Pragma("unroll") \
            for (int t = 0; t < 10; ++t) { \
                Bf[t][0] = s2r[8 * t]; \
                Bf[t][1] = s2r[4 * S2S + 8 * t]; \
            } \
            _Pragma("unroll") \
            for (int u = 0; u < 8; ++u) { \
                mma_tf32(frag[0][u], A[0], Bf[u][0],     Bf[u][1]); \
                mma_tf32(frag[1][u], A[1], Bf[u + 2][0], Bf[u + 2][1]); \
            } \
        } while (0)

        STEP_A(0);  STEP_A(1);  STEP_A(2);  STEP_A(3);
        STEP_A(4);  STEP_A(5);  STEP_A(6);  STEP_A(7);
        STEP_A(8);  STEP_A(9);  STEP_A(10); STEP_A(11);
        STEP_A(12); STEP_A(13); STEP_A(14); STEP_A(15);

        __syncthreads();
#pragma unroll
        for (int i = 0; i < 2; ++i)
#pragma unroll
            for (int u = 0; u < 8; ++u)
#pragma unroll
                for (int c4 = 0; c4 < 4; ++c4) {
                    const int r  = gid + ((c4 >= 2) ? 8 : 0);
                    const int cc = 2 * tig + (c4 & 1);
                    const int d  = 8 * u + cc - r - 1;
                    if (d >= 0 && d < D_)
                        smf[d * STG_S + xw + 16 * i + r] = lrelu(frag[i][u][c4]);
                }
        __syncthreads();

        float* ob = out + ((b * D_) * H_ + y) * W_;
#pragma unroll
        for (int s = 0; s < 12; ++s) {
            const int qid = tid + s * NT;
            const int d   = qid >> 6;
            const int xq  = (qid & 63) * 4;
            float4 v = *(const float4*)(smf + d * STG_S + xq);
            *(float4*)(ob + d * HW_ + xq) = v;
        }
    } else {
        // ================= B path: half row, warp = m16 =====================
        const int idx = bid - NA_CTAS;
        const int row = NA_CTAS + (idx >> 1);
        const int x0  = (idx & 1) * 128;
        const int b   = row >> 7;
        const int y   = row & (H_ - 1);
        const int xw  = 16 * w;

        const float* f1p = f1 + (b * C_ * H_ + y) * W_;
        const float* f2p = f2 + (b * C_ * H_ + y) * W_;

        const int r8  = tid >> 5;              // 0..7
        const int qc1 = (tid & 31) * 4;        // 0..124
        // s2 fill: 8 rows x 44 quads = 352 slots over 256 threads (2 passes)
        const int i2a = tid;
        const int i2b = tid + NT;
        const int r2a = i2a / 44, k2a = (i2a % 44) * 4;
        const int r2b = i2b / 44, k2b = (i2b % 44) * 4;
        const int gxa = x0 - 48 + k2a;
        const int gxb = x0 - 48 + k2b;
        const bool va = (gxa >= 0);
        const bool vb = (i2b < 352) && (gxb >= 0);

#define ISSUE_B(K) do { \
            constexpr int _st = (K) & 3; \
            const uint32_t s1b = smem_base + (_st * STAGE_W) * 4; \
            const uint32_t s2b = s1b + (CK * S1S) * 4; \
            CP16(s1b + (r8 * S1S + qc1) * 4, f1p + ((K) * CK + r8) * HW_ + x0 + qc1); \
            if (va) CP16(s2b + (r2a * S2S + k2a) * 4, f2p + ((K) * CK + r2a) * HW_ + gxa); \
            if (vb) CP16(s2b + (r2b * S2S + k2b) * 4, f2p + ((K) * CK + r2b) * HW_ + gxb); \
            CP_COMMIT(); \
        } while (0)

        float frag[8][4];
#pragma unroll
        for (int u = 0; u < 8; ++u)
#pragma unroll
            for (int c4 = 0; c4 < 4; ++c4) frag[u][c4] = 0.0f;

        ISSUE_B(0); ISSUE_B(1); ISSUE_B(2);

        const int a_off = tig * S1S + xw + gid;
        const int b_off = tig * S2S + xw + gid;

#define STEP_B(K) do { \
            wait_ct<K>(); \
            __syncthreads(); \
            if ((K) + 3 < NCH) ISSUE_B((K) + 3 < NCH ? (K) + 3 : 0); \
            constexpr int _st = (K) & 3; \
            const uint32_t* s1r = (const uint32_t*)(smf + _st * STAGE_W) + a_off; \
            const uint32_t* s2r = (const uint32_t*)(smf + _st * STAGE_W + CK * S1S) + b_off; \
            uint32_t A[4]; \
            A[0] = cvt_tf32(s1r[0]); \
            A[1] = cvt_tf32(s1r[8]); \
            A[2] = cvt_tf32(s1r[4 * S1S]); \
            A[3] = cvt_tf32(s1r[4 * S1S + 8]); \
            uint32_t Bf[8][2]; \
            _Pragma("unroll") \
            for (int t = 0; t < 8; ++t) { \
                Bf[t][0] = s2r[8 * t]; \
                Bf[t][1] = s2r[4 * S2S + 8 * t]; \
            } \
            _Pragma("unroll") \
            for (int u = 0; u < 8; ++u) \
                mma_tf32(frag[u], A, Bf[u][0], Bf[u][1]); \
        } while (0)

        STEP_B(0);  STEP_B(1);  STEP_B(2);  STEP_B(3);
        STEP_B(4);  STEP_B(5);  STEP_B(6);  STEP_B(7);
        STEP_B(8);  STEP_B(9);  STEP_B(10); STEP_B(11);
        STEP_B(12); STEP_B(13); STEP_B(14); STEP_B(15);

        __syncthreads();
#pragma unroll
        for (int u = 0; u < 8; ++u)
#pragma unroll
            for (int c4 = 0; c4 < 4; ++c4) {
                const int r  = gid + ((c4 >= 2) ? 8 : 0);
                const int cc = 2 * tig + (c4 & 1);
                const int d  = 8 * u + cc - r - 1;
                if (d >= 0 && d < D_)
                    smf[d * STG_S + x0 + xw + r] = lrelu(frag[u][c4]);
            }
        __syncthreads();

        float* ob = out + ((b * D_) * H_ + y) * W_;
#pragma unroll
        for (int s = 0; s < 6; ++s) {
            const int qid = tid + s * NT;
            const int d   = qid >> 5;
            const int xq  = (qid & 31) * 4 + x0;
            float4 v = *(const float4*)(smf + d * STG_S + xq);
            *(float4*)(ob + d * HW_ + xq) = v;
        }
    }
}

extern "C" void kernel_launch(void* const* d_in, const int* in_sizes, int n_in,
                              void* d_out, int out_size) {
    (void)in_sizes; (void)n_in; (void)out_size;
    const float* f1 = (const float*)d_in[0];
    const float* f2 = (const float*)d_in[1];
    float* out = (float*)d_out;

    cudaFuncSetAttribute(corr1d_tc, cudaFuncAttributeMaxDynamicSharedMemorySize,
                         SMEM_BYTES);
    corr1d_tc<<<GRID, NT, SMEM_BYTES>>>(f1, f2, out);
}

// round 16
// speedup vs baseline: 1.0263x; 1.0263x over previous
#include <cuda_runtime.h>
#include <cstdint>

// Correlation1dCost: feat [B,C,H,W] f32 -> out [B,D,H,W] f32
// out[b,d,y,x] = leakyrelu_0.1( sum_c f1[b,c,y,x] * f2[b,c,y,x+d-47] ), zero OOB
// Band-GEMM on tensor cores (m16n8k8 tf32), cp.async 6-stage depth-5 pipeline.
// Hybrid grid: rows 0..911 full-row CTAs; rows 912..1023 half-row tail CTAs.
// Output written with st.global.cs (streaming, evict-first): write data is
// never re-read, so keeping it out of L2 preserves capacity for the read stream.
#define B_ 8
#define C_ 128
#define H_ 128
#define W_ 256
#define D_ 48
#define HW_ (H_ * W_)

#define CK 8               // channels per chunk = one k8 MMA step
#define NCH 16             // chunks
#define NSTG 6             // pipeline stages (5 chunks in flight)
#define S1S 264            // s1 row stride (words), %32==8 -> conflict-free frags
#define S2S 328            // s2 row stride (words), %32==8
#define S2OFF 48           // A-path: phys col = x' + 48
#define NT 256             // 8 warps
#define STG_S 260          // epilogue staging row stride

#define NA_CTAS 912        // full-row CTAs (rows 0..911)
#define NB_ROWS (B_ * H_ - NA_CTAS)       // 112 rows
#define GRID (NA_CTAS + 2 * NB_ROWS)      // 1136

#define STAGE_W (CK * (S1S + S2S))        // 4736 words per stage
#define SMEM_BYTES (NSTG * STAGE_W * 4)   // 113664 B -> 2 CTAs/SM

extern __shared__ float smf[];

#define CP16(dst, src) asm volatile( \
    "cp.async.cg.shared.global [%0], [%1], 16;\n" :: "r"(dst), "l"(src))
#define CP_COMMIT() asm volatile("cp.async.commit_group;\n" ::: "memory")
#define CP_WAIT(n)  asm volatile("cp.async.wait_group %0;\n" :: "n"(n) : "memory")

// streaming (evict-first) 16B store
__device__ __forceinline__ void stg_cs(float* p, float4 v) {
    asm volatile("st.global.cs.v4.f32 [%0], {%1,%2,%3,%4};"
                 :: "l"(p), "f"(v.x), "f"(v.y), "f"(v.z), "f"(v.w) : "memory");
}

__device__ __forceinline__ uint32_t cvt_tf32(uint32_t f) {
    uint32_t u;
    asm("cvt.rna.tf32.f32 %0, %1;" : "=r"(u) : "r"(f));
    return u;
}

__device__ __forceinline__ void mma_tf32(float d[4], const uint32_t a[4],
                                         uint32_t b0, uint32_t b1) {
    asm volatile(
        "mma.sync.aligned.m16n8k8.row.col.f32.tf32.tf32.f32 "
        "{%0,%1,%2,%3}, {%4,%5,%6,%7}, {%8,%9}, {%0,%1,%2,%3};"
        : "+f"(d[0]), "+f"(d[1]), "+f"(d[2]), "+f"(d[3])
        : "r"(a[0]), "r"(a[1]), "r"(a[2]), "r"(a[3]), "r"(b0), "r"(b1));
}

__device__ __forceinline__ float lrelu(float v) { return fmaxf(v, 0.1f * v); }

// wait ladder: ensure chunks <= k have landed
__device__ __forceinline__ void wait_for(int k) {
    const int rem = NCH - 1 - k;
    if (rem >= 4)      CP_WAIT(4);
    else if (rem == 3) CP_WAIT(3);
    else if (rem == 2) CP_WAIT(2);
    else if (rem == 1) CP_WAIT(1);
    else               CP_WAIT(0);
}

__global__ __launch_bounds__(NT, 2)
void corr1d_tc(const float* __restrict__ f1,
               const float* __restrict__ f2,
               float* __restrict__ out) {
    const int tid  = threadIdx.x;
    const int bid  = blockIdx.x;
    const int lane = tid & 31;
    const int w    = tid >> 5;
    const int gid  = lane >> 2;                // 0..7
    const int tig  = lane & 3;                 // 0..3
    const uint32_t smem_base = (uint32_t)__cvta_generic_to_shared(smf);

    // zero s2 left pads (phys cols [0,48)) for all stages ONCE.
    for (int i = tid; i < NSTG * CK * S2OFF; i += NT) {
        int st = i / (CK * S2OFF);
        int r  = i % (CK * S2OFF);
        smf[st * STAGE_W + CK * S1S + (r / S2OFF) * S2S + (r % S2OFF)] = 0.0f;
    }

    if (bid < NA_CTAS) {
        // ================= A path: full row, warp = m32 =====================
        const int b  = bid >> 7;
        const int y  = bid & (H_ - 1);
        const int xw = 32 * w;

        const float* f1p = f1 + (b * C_ * H_ + y) * W_;
        const float* f2p = f2 + (b * C_ * H_ + y) * W_;

        const int qr = tid >> 6;               // 0..3 -> rows qr, qr+4
        const int qc = (tid & 63) * 4;         // 0..252

        auto issue = [&](int k, int st) {
            const int c0 = k * CK;
            const uint32_t s1b = smem_base + (st * STAGE_W) * 4;
            const uint32_t s2b = s1b + (CK * S1S) * 4;
#pragma unroll
            for (int j = 0; j < 2; ++j) {
                const int r = qr + 4 * j;
                CP16(s1b + (r * S1S + qc) * 4,         f1p + (c0 + r) * HW_ + qc);
                CP16(s2b + (r * S2S + S2OFF + qc) * 4, f2p + (c0 + r) * HW_ + qc);
            }
        };

        float frag[2][8][4];
#pragma unroll
        for (int i = 0; i < 2; ++i)
#pragma unroll
            for (int u = 0; u < 8; ++u)
#pragma unroll
                for (int c4 = 0; c4 < 4; ++c4) frag[i][u][c4] = 0.0f;

        // prologue: 5 chunks in flight
        issue(0, 0); CP_COMMIT();
        issue(1, 1); CP_COMMIT();
        issue(2, 2); CP_COMMIT();
        issue(3, 3); CP_COMMIT();
        issue(4, 4); CP_COMMIT();

        const int a_row = tig * S1S;
        const int b_row = tig * S2S;
        int st = 0, st_n = 5;

        for (int k = 0; k < NCH; ++k) {
            wait_for(k);
            __syncthreads();                   // stage k visible; stage (k-1) sealed
            if (k + 5 < NCH) {
                issue(k + 5, st_n); CP_COMMIT();
                if (++st_n == NSTG) st_n = 0;
            }

            const uint32_t* s1q = (const uint32_t*)(smf + st * STAGE_W);
            const uint32_t* s2q = s1q + CK * S1S;
            if (++st == NSTG) st = 0;

            const uint32_t* s1r = s1q + a_row + xw + gid;
            const uint32_t* s2r = s2q + b_row + xw + gid;

            uint32_t A[2][4];
#pragma unroll
            for (int i = 0; i < 2; ++i) {
                A[i][0] = cvt_tf32(s1r[16 * i]);
                A[i][1] = cvt_tf32(s1r[16 * i + 8]);
                A[i][2] = cvt_tf32(s1r[4 * S1S + 16 * i]);
                A[i][3] = cvt_tf32(s1r[4 * S1S + 16 * i + 8]);
            }
            uint32_t Bf[10][2];
#pragma unroll
            for (int t = 0; t < 10; ++t) {
                Bf[t][0] = s2r[8 * t];
                Bf[t][1] = s2r[4 * S2S + 8 * t];
            }
#pragma unroll
            for (int u = 0; u < 8; ++u) {
                mma_tf32(frag[0][u], A[0], Bf[u][0],     Bf[u][1]);
                mma_tf32(frag[1][u], A[1], Bf[u + 2][0], Bf[u + 2][1]);
            }
        }

        __syncthreads();
#pragma unroll
        for (int i = 0; i < 2; ++i)
#pragma unroll
            for (int u = 0; u < 8; ++u)
#pragma unroll
                for (int c4 = 0; c4 < 4; ++c4) {
                    const int r  = gid + ((c4 >= 2) ? 8 : 0);
                    const int cc = 2 * tig + (c4 & 1);
                    const int d  = 8 * u + cc - r - 1;
                    if (d >= 0 && d < D_)
                        smf[d * STG_S + xw + 16 * i + r] = lrelu(frag[i][u][c4]);
                }
        __syncthreads();

        float* ob = out + ((b * D_) * H_ + y) * W_;
#pragma unroll
        for (int s = 0; s < 12; ++s) {
            const int qid = tid + s * NT;
            const int d   = qid >> 6;
            const int xq  = (qid & 63) * 4;
            float4 v = *(const float4*)(smf + d * STG_S + xq);
            stg_cs(ob + d * HW_ + xq, v);
        }
    } else {
        // ================= B path: half row, warp = m16 =====================
        const int idx = bid - NA_CTAS;
        const int row = NA_CTAS + (idx >> 1);
        const int x0  = (idx & 1) * 128;
        const int b   = row >> 7;
        const int y   = row & (H_ - 1);
        const int xw  = 16 * w;

        const float* f1p = f1 + (b * C_ * H_ + y) * W_;
        const float* f2p = f2 + (b * C_ * H_ + y) * W_;

        // s1: 8 rows x 32 quads = 256 (1/thread); s2: 8 rows x 44 quads = 352
        const int r8  = tid >> 5;              // 0..7
        const int qc1 = (tid & 31) * 4;        // 0..124

        auto issueB = [&](int k, int st) {
            const int c0 = k * CK;
            const uint32_t s1b = smem_base + (st * STAGE_W) * 4;
            const uint32_t s2b = s1b + (CK * S1S) * 4;
            CP16(s1b + (r8 * S1S + qc1) * 4, f1p + (c0 + r8) * HW_ + x0 + qc1);
            // s2: phys k in [0,176): x' = x0 - 48 + k
#pragma unroll
            for (int s = 0; s < 2; ++s) {
                const int i = tid + s * NT;
                if (i < 352) {
                    const int r  = i / 44;
                    const int kq = (i % 44) * 4;
                    const int gx = x0 - 48 + kq;
                    if (gx >= 0)
                        CP16(s2b + (r * S2S + kq) * 4, f2p + (c0 + r) * HW_ + gx);
                }
            }
        };

        float frag[8][4];
#pragma unroll
        for (int u = 0; u < 8; ++u)
#pragma unroll
            for (int c4 = 0; c4 < 4; ++c4) frag[u][c4] = 0.0f;

        issueB(0, 0); CP_COMMIT();
        issueB(1, 1); CP_COMMIT();
        issueB(2, 2); CP_COMMIT();
        issueB(3, 3); CP_COMMIT();
        issueB(4, 4); CP_COMMIT();

        const int a_row = tig * S1S;
        const int b_row = tig * S2S;
        int st = 0, st_n = 5;

        for (int k = 0; k < NCH; ++k) {
            wait_for(k);
            __syncthreads();
            if (k + 5 < NCH) {
                issueB(k + 5, st_n); CP_COMMIT();
                if (++st_n == NSTG) st_n = 0;
            }

            const uint32_t* s1q = (const uint32_t*)(smf + st * STAGE_W);
            const uint32_t* s2q = s1q + CK * S1S;
            if (++st == NSTG) st = 0;

            const uint32_t* s1r = s1q + a_row + xw + gid;
            const uint32_t* s2r = s2q + b_row + xw + gid;

            uint32_t A[4];
            A[0] = cvt_tf32(s1r[0]);
            A[1] = cvt_tf32(s1r[8]);
            A[2] = cvt_tf32(s1r[4 * S1S]);
            A[3] = cvt_tf32(s1r[4 * S1S + 8]);

            uint32_t Bf[8][2];
#pragma unroll
            for (int t = 0; t < 8; ++t) {
                Bf[t][0] = s2r[8 * t];
                Bf[t][1] = s2r[4 * S2S + 8 * t];
            }
#pragma unroll
            for (int u = 0; u < 8; ++u)
                mma_tf32(frag[u], A, Bf[u][0], Bf[u][1]);
        }

        __syncthreads();
        // x = x0 + xw + r ; d = 8u + cc - r - 1
#pragma unroll
        for (int u = 0; u < 8; ++u)
#pragma unroll
            for (int c4 = 0; c4 < 4; ++c4) {
                const int r  = gid + ((c4 >= 2) ? 8 : 0);
                const int cc = 2 * tig + (c4 & 1);
                const int d  = 8 * u + cc - r - 1;
                if (d >= 0 && d < D_)
                    smf[d * STG_S + x0 + xw + r] = lrelu(frag[u][c4]);
            }
        __syncthreads();

        float* ob = out + ((b * D_) * H_ + y) * W_;
#pragma unroll
        for (int s = 0; s < 6; ++s) {
            const int qid = tid + s * NT;
            const int d   = qid >> 5;              // 0..47
            const int xq  = (qid & 31) * 4 + x0;
            float4 v = *(const float4*)(smf + d * STG_S + xq);
            stg_cs(ob + d * HW_ + xq, v);
        }
    }
}

extern "C" void kernel_launch(void* const* d_in, const int* in_sizes, int n_in,
                              void* d_out, int out_size) {
    (void)in_sizes; (void)n_in; (void)out_size;
    const float* f1 = (const float*)d_in[0];
    const float* f2 = (const float*)d_in[1];
    float* out = (float*)d_out;

    cudaFuncSetAttribute(corr1d_tc, cudaFuncAttributeMaxDynamicSharedMemorySize,
                         SMEM_BYTES);
    corr1d_tc<<<GRID, NT, SMEM_BYTES>>>(f1, f2, out);
}

// round 17
// speedup vs baseline: 1.0309x; 1.0044x over previous
#include <cuda_runtime.h>
#include <cstdint>

// Correlation1dCost: feat [B,C,H,W] f32 -> out [B,D,H,W] f32
// out[b,d,y,x] = leakyrelu_0.1( sum_c f1[b,c,y,x] * f2[b,c,y,x+d-47] ), zero OOB
// Band-GEMM on tensor cores (m16n8k8 tf32), cp.async 6-stage depth-5 pipeline.
// Hybrid grid: rows 0..911 full-row CTAs; rows 912..1023 half-row tail CTAs.
// A-path epilogue is PER-WARP (no CTA barriers): warp-private staging transpose,
// __syncwarp, streaming stores -> fast warps drain while slow warps finish MMAs.
#define B_ 8
#define C_ 128
#define H_ 128
#define W_ 256
#define D_ 48
#define HW_ (H_ * W_)

#define CK 8               // channels per chunk = one k8 MMA step
#define NCH 16             // chunks
#define NSTG 6             // pipeline stages (5 chunks in flight)
#define S1S 264            // s1 row stride (words), %32==8 -> conflict-free frags
#define S2S 328            // s2 row stride (words), %32==8
#define S2OFF 48           // A-path: phys col = x' + 48
#define NT 256             // 8 warps
#define STG_S 260          // B-path CTA staging row stride
#define WST 36             // A-path per-warp staging row stride (conflict-free)

#define NA_CTAS 912
#define NB_ROWS (B_ * H_ - NA_CTAS)       // 112
#define GRID (NA_CTAS + 2 * NB_ROWS)      // 1136

#define STAGE_W (CK * (S1S + S2S))        // 4736 words per stage
#define SMEM_BYTES (NSTG * STAGE_W * 4)   // 113664 B -> 2 CTAs/SM

extern __shared__ float smf[];

#define CP16(dst, src) asm volatile( \
    "cp.async.cg.shared.global [%0], [%1], 16;\n" :: "r"(dst), "l"(src))
#define CP_COMMIT() asm volatile("cp.async.commit_group;\n" ::: "memory")
#define CP_WAIT(n)  asm volatile("cp.async.wait_group %0;\n" :: "n"(n) : "memory")

// streaming (evict-first) 16B store
__device__ __forceinline__ void stg_cs(float* p, float4 v) {
    asm volatile("st.global.cs.v4.f32 [%0], {%1,%2,%3,%4};"
                 :: "l"(p), "f"(v.x), "f"(v.y), "f"(v.z), "f"(v.w) : "memory");
}

__device__ __forceinline__ uint32_t cvt_tf32(uint32_t f) {
    uint32_t u;
    asm("cvt.rna.tf32.f32 %0, %1;" : "=r"(u) : "r"(f));
    return u;
}

__device__ __forceinline__ void mma_tf32(float d[4], const uint32_t a[4],
                                         uint32_t b0, uint32_t b1) {
    asm volatile(
        "mma.sync.aligned.m16n8k8.row.col.f32.tf32.tf32.f32 "
        "{%0,%1,%2,%3}, {%4,%5,%6,%7}, {%8,%9}, {%0,%1,%2,%3};"
        : "+f"(d[0]), "+f"(d[1]), "+f"(d[2]), "+f"(d[3])
        : "r"(a[0]), "r"(a[1]), "r"(a[2]), "r"(a[3]), "r"(b0), "r"(b1));
}

__device__ __forceinline__ float lrelu(float v) { return fmaxf(v, 0.1f * v); }

// wait ladder: ensure chunks <= k have landed
__device__ __forceinline__ void wait_for(int k) {
    const int rem = NCH - 1 - k;
    if (rem >= 4)      CP_WAIT(4);
    else if (rem == 3) CP_WAIT(3);
    else if (rem == 2) CP_WAIT(2);
    else if (rem == 1) CP_WAIT(1);
    else               CP_WAIT(0);
}

__global__ __launch_bounds__(NT, 2)
void corr1d_tc(const float* __restrict__ f1,
               const float* __restrict__ f2,
               float* __restrict__ out) {
    const int tid  = threadIdx.x;
    const int bid  = blockIdx.x;
    const int lane = tid & 31;
    const int w    = tid >> 5;
    const int gid  = lane >> 2;                // 0..7
    const int tig  = lane & 3;                 // 0..3
    const uint32_t smem_base = (uint32_t)__cvta_generic_to_shared(smf);

    // zero s2 left pads (phys cols [0,48)) for all stages ONCE.
    for (int i = tid; i < NSTG * CK * S2OFF; i += NT) {
        int st = i / (CK * S2OFF);
        int r  = i % (CK * S2OFF);
        smf[st * STAGE_W + CK * S1S + (r / S2OFF) * S2S + (r % S2OFF)] = 0.0f;
    }

    if (bid < NA_CTAS) {
        // ================= A path: full row, warp = m32 =====================
        const int b  = bid >> 7;
        const int y  = bid & (H_ - 1);
        const int xw = 32 * w;

        const float* f1p = f1 + (b * C_ * H_ + y) * W_;
        const float* f2p = f2 + (b * C_ * H_ + y) * W_;

        const int qr = tid >> 6;               // 0..3 -> rows qr, qr+4
        const int qc = (tid & 63) * 4;         // 0..252

        auto issue = [&](int k, int st) {
            const int c0 = k * CK;
            const uint32_t s1b = smem_base + (st * STAGE_W) * 4;
            const uint32_t s2b = s1b + (CK * S1S) * 4;
#pragma unroll
            for (int j = 0; j < 2; ++j) {
                const int r = qr + 4 * j;
                CP16(s1b + (r * S1S + qc) * 4,         f1p + (c0 + r) * HW_ + qc);
                CP16(s2b + (r * S2S + S2OFF + qc) * 4, f2p + (c0 + r) * HW_ + qc);
            }
        };

        float frag[2][8][4];
#pragma unroll
        for (int i = 0; i < 2; ++i)
#pragma unroll
            for (int u = 0; u < 8; ++u)
#pragma unroll
                for (int c4 = 0; c4 < 4; ++c4) frag[i][u][c4] = 0.0f;

        issue(0, 0); CP_COMMIT();
        issue(1, 1); CP_COMMIT();
        issue(2, 2); CP_COMMIT();
        issue(3, 3); CP_COMMIT();
        issue(4, 4); CP_COMMIT();

        const int a_row = tig * S1S;
        const int b_row = tig * S2S;
        int st = 0, st_n = 5;

        for (int k = 0; k < NCH; ++k) {
            wait_for(k);
            __syncthreads();                   // stage k visible; stage (k-1) sealed
            if (k + 5 < NCH) {
                issue(k + 5, st_n); CP_COMMIT();
                if (++st_n == NSTG) st_n = 0;
            }

            const uint32_t* s1q = (const uint32_t*)(smf + st * STAGE_W);
            const uint32_t* s2q = s1q + CK * S1S;
            if (++st == NSTG) st = 0;

            const uint32_t* s1r = s1q + a_row + xw + gid;
            const uint32_t* s2r = s2q + b_row + xw + gid;

            uint32_t A[2][4];
#pragma unroll
            for (int i = 0; i < 2; ++i) {
                A[i][0] = cvt_tf32(s1r[16 * i]);
                A[i][1] = cvt_tf32(s1r[16 * i + 8]);
                A[i][2] = cvt_tf32(s1r[4 * S1S + 16 * i]);
                A[i][3] = cvt_tf32(s1r[4 * S1S + 16 * i + 8]);
            }
            uint32_t Bf[10][2];
#pragma unroll
            for (int t = 0; t < 10; ++t) {
                Bf[t][0] = s2r[8 * t];
                Bf[t][1] = s2r[4 * S2S + 8 * t];
            }
#pragma unroll
            for (int u = 0; u < 8; ++u) {
                mma_tf32(frag[0][u], A[0], Bf[u][0],     Bf[u][1]);
                mma_tf32(frag[1][u], A[1], Bf[u + 2][0], Bf[u + 2][1]);
            }
        }

        // ---- per-warp epilogue: NO CTA barrier.
        // Warp staging lives in words [w*48*WST, (w+1)*48*WST) = [0, 13824)
        // which overlaps only stages 0..2; after the k=15 barrier only stage 3
        // (words 14208+) is still read by lagging warps -> safe.
        float* stg = smf + w * (D_ * WST);
#pragma unroll
        for (int i = 0; i < 2; ++i)
#pragma unroll
            for (int u = 0; u < 8; ++u)
#pragma unroll
                for (int c4 = 0; c4 < 4; ++c4) {
                    const int r  = gid + ((c4 >= 2) ? 8 : 0);
                    const int cc = 2 * tig + (c4 & 1);
                    const int d  = 8 * u + cc - r - 1;
                    if (d >= 0 && d < D_)
                        stg[d * WST + 16 * i + r] = lrelu(frag[i][u][c4]);
                }
        __syncwarp();

        const int g8 = lane >> 3;              // 0..3 (d subgroup)
        const int l8 = lane & 7;               // 0..7 (x quad)
        float* ob = out + ((b * D_) * H_ + y) * W_ + xw;
#pragma unroll
        for (int it = 0; it < 12; ++it) {
            const int d = it * 4 + g8;         // 0..47
            float4 v = *(const float4*)(stg + d * WST + l8 * 4);
            stg_cs(ob + d * HW_ + l8 * 4, v);
        }
    } else {
        // ================= B path: half row, warp = m16 (unchanged) ==========
        const int idx = bid - NA_CTAS;
        const int row = NA_CTAS + (idx >> 1);
        const int x0  = (idx & 1) * 128;
        const int b   = row >> 7;
        const int y   = row & (H_ - 1);
        const int xw  = 16 * w;

        const float* f1p = f1 + (b * C_ * H_ + y) * W_;
        const float* f2p = f2 + (b * C_ * H_ + y) * W_;

        const int r8  = tid >> 5;              // 0..7
        const int qc1 = (tid & 31) * 4;        // 0..124

        auto issueB = [&](int k, int st) {
            const int c0 = k * CK;
            const uint32_t s1b = smem_base + (st * STAGE_W) * 4;
            const uint32_t s2b = s1b + (CK * S1S) * 4;
            CP16(s1b + (r8 * S1S + qc1) * 4, f1p + (c0 + r8) * HW_ + x0 + qc1);
#pragma unroll
            for (int s = 0; s < 2; ++s) {
                const int i = tid + s * NT;
                if (i < 352) {
                    const int r  = i / 44;
                    const int kq = (i % 44) * 4;
                    const int gx = x0 - 48 + kq;
                    if (gx >= 0)
                        CP16(s2b + (r * S2S + kq) * 4, f2p + (c0 + r) * HW_ + gx);
                }
            }
        };

        float frag[8][4];
#pragma unroll
        for (int u = 0; u < 8; ++u)
#pragma unroll
            for (int c4 = 0; c4 < 4; ++c4) frag[u][c4] = 0.0f;

        issueB(0, 0); CP_COMMIT();
        issueB(1, 1); CP_COMMIT();
        issueB(2, 2); CP_COMMIT();
        issueB(3, 3); CP_COMMIT();
        issueB(4, 4); CP_COMMIT();

        const int a_row = tig * S1S;
        const int b_row = tig * S2S;
        int st = 0, st_n = 5;

        for (int k = 0; k < NCH; ++k) {
            wait_for(k);
            __syncthreads();
            if (k + 5 < NCH) {
                issueB(k + 5, st_n); CP_COMMIT();
                if (++st_n == NSTG) st_n = 0;
            }

            const uint32_t* s1q = (const uint32_t*)(smf + st * STAGE_W);
            const uint32_t* s2q = s1q + CK * S1S;
            if (++st == NSTG) st = 0;

            const uint32_t* s1r = s1q + a_row + xw + gid;
            const uint32_t* s2r = s2q + b_row + xw + gid;

            uint32_t A[4];
            A[0] = cvt_tf32(s1r[0]);
            A[1] = cvt_tf32(s1r[8]);
            A[2] = cvt_tf32(s1r[4 * S1S]);
            A[3] = cvt_tf32(s1r[4 * S1S + 8]);

            uint32_t Bf[8][2];
#pragma unroll
            for (int t = 0; t < 8; ++t) {
                Bf[t][0] = s2r[8 * t];
                Bf[t][1] = s2r[4 * S2S + 8 * t];
            }
#pragma unroll
            for (int u = 0; u < 8; ++u)
                mma_tf32(frag[u], A, Bf[u][0], Bf[u][1]);
        }

        __syncthreads();
#pragma unroll
        for (int u = 0; u < 8; ++u)
#pragma unroll
            for (int c4 = 0; c4 < 4; ++c4) {
                const int r  = gid + ((c4 >= 2) ? 8 : 0);
                const int cc = 2 * tig + (c4 & 1);
                const int d  = 8 * u + cc - r - 1;
                if (d >= 0 && d < D_)
                    smf[d * STG_S + x0 + xw + r] = lrelu(frag[u][c4]);
            }
        __syncthreads();

        float* ob = out + ((b * D_) * H_ + y) * W_;
#pragma unroll
        for (int s = 0; s < 6; ++s) {
            const int qid = tid + s * NT;
            const int d   = qid >> 5;
            const int xq  = (qid & 31) * 4 + x0;
            float4 v = *(const float4*)(smf + d * STG_S + xq);
            stg_cs(ob + d * HW_ + xq, v);
        }
    }
}

extern "C" void kernel_launch(void* const* d_in, const int* in_sizes, int n_in,
                              void* d_out, int out_size) {
    (void)in_sizes; (void)n_in; (void)out_size;
    const float* f1 = (const float*)d_in[0];
    const float* f2 = (const float*)d_in[1];
    float* out = (float*)d_out;

    cudaFuncSetAttribute(corr1d_tc, cudaFuncAttributeMaxDynamicSharedMemorySize,
                         SMEM_BYTES);
    corr1d_tc<<<GRID, NT, SMEM_BYTES>>>(f1, f2, out);
}